// round 11
// baseline (speedup 1.0000x reference)
#include <cuda_runtime.h>
#include <cstdint>

#define B_  8
#define T_  4096
#define DI  256
#define DO  256
#define M_TOTAL (B_ * T_)      // 32768

#define NCH   64               // half-chunks per sequence (apply granularity)
#define CHUNK (T_ / NCH)       // 64 steps per apply chunk
#define MTILE 128              // GEMM m-tile = one 128-step carry chunk

// Scratch: interleaved (a, b) = (1-f, f*x) pairs, [M_TOTAL][DO] float2 = 64 MB
__device__ float g_ab[(size_t)M_TOTAL * DO * 2];
// Per-(b, half-chunk, o) carry composition and resolved chunk-entry state
__device__ float g_cA[B_ * NCH * DO];
__device__ float g_cS[B_ * NCH * DO];
__device__ float g_hin[B_ * NCH * DO];

__device__ __forceinline__ uint32_t f2tf32(float x) {
    uint32_t r;
    asm("cvt.rna.tf32.f32 %0, %1;" : "=r"(r) : "f"(x));
    return r;
}

// ---- fragment-major smem layout ----
// Block = one mma fragment tile (A: 16m x 8k, W: 8o x 8k both matrices),
// 32 lanes x 4 words; +8 pad words staggers staging-write banks.
#define BLKF   136                 // words per block (128 + 8 pad)
#define W_OFF  (32 * BLKF)         // A blocks: 8 mblk x 4 kblk
#define STG_F  (2 * 32 * BLKF)     // words per stage (A + W)
#define SMEM_WORDS (2 * STG_F)     // 17408 words = 69632 B (also holds sAB 64 KB)

#define MMA_TF32(d, a, b0, b1)                                            \
    asm volatile(                                                         \
        "mma.sync.aligned.m16n8k8.row.col.f32.tf32.tf32.f32 "            \
        "{%0,%1,%2,%3}, {%4,%5,%6,%7}, {%8,%9}, {%0,%1,%2,%3};"          \
        : "+f"((d)[0]), "+f"((d)[1]), "+f"((d)[2]), "+f"((d)[3])          \
        : "r"((a)[0]), "r"((a)[1]), "r"((a)[2]), "r"((a)[3]),             \
          "r"(b0), "r"(b1))

// CTA: 256 threads, tile M=128 x O=64, both projections + fused chunk-carry.
// Grid: (DO/64, M_TOTAL/128) = (4, 256). Register-prefetch K pipeline,
// fragment-major smem -> one LDS.128 per fragment.
__global__ __launch_bounds__(256, 2) void qrnn_gemm(
    const float* __restrict__ in,    // [M_TOTAL, DI]
    const float* __restrict__ mask,  // [M_TOTAL]
    const float* __restrict__ Wx,    // [DO, DI]
    const float* __restrict__ bx,    // [DO]
    const float* __restrict__ Wf,    // [DO, DI]
    const float* __restrict__ bf)    // [DO]
{
    extern __shared__ uint32_t smem[];
    __shared__ float2 sSeg[4][64];       // per-segment (A, S) carry partials

    const int tid   = threadIdx.x;
    const int lane  = tid & 31;
    const int warp  = tid >> 5;
    const int warpM = warp & 3;      // 4 warps along M (32 rows each)
    const int warpN = warp >> 2;     // 2 warps along O (32 cols each)
    const int gid   = lane >> 2;     // 0..7
    const int tig   = lane & 3;      // 0..3

    const int m0 = blockIdx.y * MTILE;
    const int o0 = blockIdx.x * 64;

    float accx[2][4][4];
    float accf[2][4][4];
#pragma unroll
    for (int mf = 0; mf < 2; mf++)
#pragma unroll
        for (int nf = 0; nf < 4; nf++)
#pragma unroll
            for (int c = 0; c < 4; c++) { accx[mf][nf][c] = 0.f; accf[mf][nf][c] = 0.f; }

    // ---- per-thread staging coords: 4 A quads + 4 W quads (fixed) ----
    float4 pa[4], pw[4];
    int arow[4], acol;                  // gmem coords
    int wrow[4], wsel[4], wcol[4];
    int aoff[4], woff[4];               // fragment-major smem word offsets
#pragma unroll
    for (int i = 0; i < 4; i++) {
        int lin = tid + i * 256;
        // A: row r (0..127), cols c4..c4+3
        int r  = lin >> 3;
        int c4 = (lin & 7) << 2;
        arow[i] = r;
        {
            int mblk  = r >> 4, rr = r & 15;
            int kblk  = c4 >> 3, khalf = (c4 >> 2) & 1;
            aoff[i] = (mblk * 4 + kblk) * BLKF + (rr & 7) * 16 + khalf * 2 + (rr >> 3);
        }
        // W: matrix w, row o (0..63), cols c4w..c4w+3
        int w   = lin >> 9;
        int rem = lin & 511;
        int o   = rem >> 3;
        int c4w = (rem & 7) << 2;
        wsel[i] = w; wrow[i] = o; wcol[i] = c4w;
        {
            int oblk  = o >> 3, g = o & 7;
            int kblk  = c4w >> 3, khalf = (c4w >> 2) & 1;
            woff[i] = W_OFF + (oblk * 4 + kblk) * BLKF + g * 16 + w * 2 + khalf;
        }
    }
    acol = (tid & 7) << 2;

    auto ldg_issue = [&](int kc) {
#pragma unroll
        for (int i = 0; i < 4; i++)
            pa[i] = *(const float4*)(in + (size_t)(m0 + arow[i]) * DI + kc + acol);
#pragma unroll
        for (int i = 0; i < 4; i++) {
            const float* Wp = wsel[i] ? Wf : Wx;
            pw[i] = *(const float4*)(Wp + (size_t)(o0 + wrow[i]) * DI + kc + wcol[i]);
        }
    };
    auto sts = [&](int s) {
        uint32_t* S = smem + s * STG_F;
#pragma unroll
        for (int i = 0; i < 4; i++) {
            uint32_t* d = S + aoff[i];
            d[0]  = f2tf32(pa[i].x); d[4]  = f2tf32(pa[i].y);
            d[8]  = f2tf32(pa[i].z); d[12] = f2tf32(pa[i].w);
        }
#pragma unroll
        for (int i = 0; i < 4; i++) {
            uint32_t* d = S + woff[i];
            d[0]  = f2tf32(pw[i].x); d[4]  = f2tf32(pw[i].y);
            d[8]  = f2tf32(pw[i].z); d[12] = f2tf32(pw[i].w);
        }
    };

    ldg_issue(0);
    sts(0);
    __syncthreads();

    const int NCHK = DI / 32;   // 8 K-chunks of 32
#pragma unroll 1
    for (int i = 0; i < NCHK; i++) {
        if (i < NCHK - 1) ldg_issue((i + 1) * 32);   // overlap with MMAs below

        const uint32_t* S  = smem + (i & 1) * STG_F;
        const uint32_t* Ab = S + lane * 4;           // A fragment base for this lane
        const uint32_t* Wb = S + W_OFF + lane * 4;   // W fragment base

#pragma unroll
        for (int ks = 0; ks < 4; ks++) {
            uint32_t a[2][4];
#pragma unroll
            for (int mf = 0; mf < 2; mf++) {
                uint4 v = *(const uint4*)(Ab + ((warpM * 2 + mf) * 4 + ks) * BLKF);
                a[mf][0] = v.x; a[mf][1] = v.y; a[mf][2] = v.z; a[mf][3] = v.w;
            }
#pragma unroll
            for (int nf = 0; nf < 4; nf++) {
                uint4 wv = *(const uint4*)(Wb + ((warpN * 4 + nf) * 4 + ks) * BLKF);
#pragma unroll
                for (int mf = 0; mf < 2; mf++) {
                    MMA_TF32(accx[mf][nf], a[mf], wv.x, wv.y);
                    MMA_TF32(accf[mf][nf], a[mf], wv.z, wv.w);
                }
            }
        }
        __syncthreads();              // all reads of stage i&1 done
        if (i < NCHK - 1) {
            sts((i + 1) & 1);
            __syncthreads();          // stage (i+1)&1 ready
        }
    }

    // ---- Epilogue: activations, write (a,b) to gmem AND smem for carry ----
    float2* sAB = (float2*)smem;       // [128 rows][64 o-cols], 64 KB (reuses stages)

#pragma unroll
    for (int mf = 0; mf < 2; mf++) {
#pragma unroll
        for (int rr = 0; rr < 2; rr++) {
            int rloc = warpM * 32 + mf * 16 + rr * 8 + gid;
            int m = m0 + rloc;
            float mk = mask[m] * 10000.0f;
#pragma unroll
            for (int nf = 0; nf < 4; nf++) {
                int oloc = warpN * 32 + nf * 8 + 2 * tig;
                int o = o0 + oloc;
                float zx0 = accx[mf][nf][rr * 2 + 0] + bx[o];
                float zx1 = accx[mf][nf][rr * 2 + 1] + bx[o + 1];
                float zf0 = accf[mf][nf][rr * 2 + 0] + bf[o] + mk;
                float zf1 = accf[mf][nf][rr * 2 + 1] + bf[o + 1] + mk;
                float x0 = __fdividef(2.0f, 1.0f + __expf(-2.0f * zx0)) - 1.0f;
                float x1 = __fdividef(2.0f, 1.0f + __expf(-2.0f * zx1)) - 1.0f;
                float f0 = __fdividef(1.0f, 1.0f + __expf(-zf0));
                float f1 = __fdividef(1.0f, 1.0f + __expf(-zf1));
                float4 st;
                st.x = 1.0f - f0; st.y = f0 * x0;
                st.z = 1.0f - f1; st.w = f1 * x1;
                *(float4*)(&g_ab[((size_t)m * DO + o) * 2]) = st;
                *(float4*)(&sAB[rloc * 64 + oloc]) = st;
            }
        }
    }
    __syncthreads();

    // ---- Fused carry: 4 segments of 32 rows -> 2 half-chunk carries ----
    {
        const int o   = tid & 63;
        const int seg = tid >> 6;          // 0..3
        const float2* col = sAB + seg * 32 * 64 + o;
        float A = 1.0f, S = 0.0f;
#pragma unroll 8
        for (int r = 0; r < 32; r++) {
            float2 v = col[r * 64];
            S = fmaf(v.x, S, v.y);
            A = A * v.x;
        }
        sSeg[seg][o] = make_float2(A, S);
    }
    __syncthreads();

    if (tid < 128) {
        const int o    = tid & 63;
        const int half = tid >> 6;         // 0..1
        float2 s0 = sSeg[2 * half][o];
        float2 s1 = sSeg[2 * half + 1][o];
        float A = s1.x * s0.x;
        float S = fmaf(s1.x, s0.y, s1.y);
        const int b = blockIdx.y >> 5;           // 32 m-tiles per sequence
        const int c = blockIdx.y & 31;           // 128-row chunk within sequence
        const int idx = (b * NCH + c * 2 + half) * DO + o0 + o;
        g_cA[idx] = A;
        g_cS[idx] = S;
    }
}

// Phase 2: per-chain serial combine over NCH half-chunk carries.
__global__ __launch_bounds__(256) void scan_combine()
{
    const int b = blockIdx.x;
    const int o = threadIdx.x;

    float h = 0.0f;
#pragma unroll 4
    for (int c = 0; c < NCH; c++) {
        const int idx = (b * NCH + c) * DO + o;
        g_hin[idx] = h;
        h = fmaf(g_cA[idx], h, g_cS[idx]);
    }
}

// Phase 3: re-scan each half-chunk from its exact entry state, writing output.
// One thread handles TWO adjacent chains: LDG.128 + STG.64 per step.
__global__ __launch_bounds__(128) void scan_apply(float* __restrict__ out)
{
    const int b = blockIdx.x;
    const int c = blockIdx.y;
    const int j = threadIdx.x;            // 0..127 -> chains 2j, 2j+1

    const size_t rowbase = ((size_t)b * T_ + (size_t)c * CHUNK) * DO;
    const float4* __restrict__ ab = (const float4*)(g_ab + (rowbase + 2 * j) * 2);
    float2* __restrict__ op = (float2*)(out + rowbase) + j;

    const int hidx = (b * NCH + c) * DO + 2 * j;
    float h0 = g_hin[hidx];
    float h1 = g_hin[hidx + 1];

#pragma unroll 8
    for (int t = 0; t < CHUNK; t++) {
        float4 v = ab[(size_t)t * (DO / 2)];   // (a0,b0,a1,b1)
        h0 = fmaf(v.x, h0, v.y);
        h1 = fmaf(v.z, h1, v.w);
        op[(size_t)t * (DO / 2)] = make_float2(h0, h1);
    }
}

extern "C" void kernel_launch(void* const* d_in, const int* in_sizes, int n_in,
                              void* d_out, int out_size)
{
    const float* in   = (const float*)d_in[0];
    const float* mask = (const float*)d_in[1];
    const float* Wx   = (const float*)d_in[2];
    const float* bx   = (const float*)d_in[3];
    const float* Wf   = (const float*)d_in[4];
    const float* bf   = (const float*)d_in[5];
    float* out = (float*)d_out;

    static bool attr_set = false;
    if (!attr_set) {
        cudaFuncSetAttribute(qrnn_gemm,
                             cudaFuncAttributeMaxDynamicSharedMemorySize,
                             SMEM_WORDS * (int)sizeof(uint32_t));
        attr_set = true;
    }

    dim3 ggrid(DO / 64, M_TOTAL / MTILE);   // (4, 256)
    qrnn_gemm<<<ggrid, 256, SMEM_WORDS * sizeof(uint32_t)>>>(in, mask, Wx, bx, Wf, bf);

    scan_combine<<<B_, 256>>>();
    dim3 sgrid(B_, NCH);                    // (8, 64)
    scan_apply<<<sgrid, 128>>>(out);
}

// round 16
// speedup vs baseline: 1.3255x; 1.3255x over previous
#include <cuda_runtime.h>
#include <cstdint>

#define B_  8
#define T_  4096
#define DI  256
#define DO  256
#define M_TOTAL (B_ * T_)      // 32768

#define NCH   64               // half-chunks per sequence (apply granularity)
#define CHUNK (T_ / NCH)       // 64 steps per apply chunk
#define MTILE 128              // GEMM m-tile = one 128-step carry chunk

// Scratch: interleaved (a, b) = (1-f, f*x) pairs, [M_TOTAL][DO] float2 = 64 MB
__device__ float g_ab[(size_t)M_TOTAL * DO * 2];
// Per-(b, half-chunk, o) carry composition and resolved chunk-entry state
__device__ float g_cA[B_ * NCH * DO];
__device__ float g_cS[B_ * NCH * DO];
__device__ float g_hin[B_ * NCH * DO];

// pack two fp32 -> f16x2 (lo = first arg)
__device__ __forceinline__ uint32_t packh2(float lo, float hi) {
    uint32_t d;
    asm("cvt.rn.f16x2.f32 %0, %1, %2;" : "=r"(d) : "f"(hi), "f"(lo));
    return d;
}

// ---- fp16 smem layout ----
// A: 128 rows x 16 words (32 f16) + 4 pad -> stride 20 words.
// W: 128 rows (Wx 0..63, Wf 64..127) x same stride.
// Fragment LDS address = 20*gid + tig + const -> bank-unique across warp.
#define ASTR      20
#define AW        (128 * ASTR)          // 2560 words
#define WW        (128 * ASTR)          // 2560 words
#define STG_W     (AW + WW)             // 5120 words per stage
#define SMEM_WORDS 16384                // max(2*STG_W=10240, sAB 16384) = 64 KB

#define MMA_F16(d, a, b0, b1)                                             \
    asm volatile(                                                         \
        "mma.sync.aligned.m16n8k16.row.col.f32.f16.f16.f32 "             \
        "{%0,%1,%2,%3}, {%4,%5,%6,%7}, {%8,%9}, {%0,%1,%2,%3};"          \
        : "+f"((d)[0]), "+f"((d)[1]), "+f"((d)[2]), "+f"((d)[3])          \
        : "r"((a)[0]), "r"((a)[1]), "r"((a)[2]), "r"((a)[3]),             \
          "r"(b0), "r"(b1))

// CTA: 256 threads, tile M=128 x O=64, both projections + fused chunk-carry.
// Grid: (DO/64, M_TOTAL/128) = (4, 256). Register-prefetch K pipeline, fp16 MMA.
__global__ __launch_bounds__(256, 2) void qrnn_gemm(
    const float* __restrict__ in,    // [M_TOTAL, DI]
    const float* __restrict__ mask,  // [M_TOTAL]
    const float* __restrict__ Wx,    // [DO, DI]
    const float* __restrict__ bx,    // [DO]
    const float* __restrict__ Wf,    // [DO, DI]
    const float* __restrict__ bf)    // [DO]
{
    extern __shared__ uint32_t smem[];
    __shared__ float2 sSeg[4][64];       // per-segment (A, S) carry partials

    const int tid   = threadIdx.x;
    const int lane  = tid & 31;
    const int warp  = tid >> 5;
    const int warpM = warp & 3;      // 4 warps along M (32 rows each)
    const int warpN = warp >> 2;     // 2 warps along O (32 cols each)
    const int gid   = lane >> 2;     // 0..7
    const int tig   = lane & 3;      // 0..3

    const int m0 = blockIdx.y * MTILE;
    const int o0 = blockIdx.x * 64;

    float accx[2][4][4];
    float accf[2][4][4];
#pragma unroll
    for (int mf = 0; mf < 2; mf++)
#pragma unroll
        for (int nf = 0; nf < 4; nf++)
#pragma unroll
            for (int c = 0; c < 4; c++) { accx[mf][nf][c] = 0.f; accf[mf][nf][c] = 0.f; }

    // Per-thread staging coords (fixed): 4 A quads, 4 W quads
    float4 pa[4], pw[4];
    int arow[4], acol;
    int wrow[4], wsel[4], wcol[4];
#pragma unroll
    for (int i = 0; i < 4; i++) {
        int lin = tid + i * 256;
        arow[i] = lin >> 3;                  // 0..127
        int w   = lin >> 9;                  // 0: Wx, 1: Wf
        int rem = lin & 511;
        wsel[i] = w;
        wrow[i] = rem >> 3;                  // 0..63
        wcol[i] = (rem & 7) << 2;            // 0..28
    }
    acol = (tid & 7) << 2;

    auto ldg_issue = [&](int kc) {
#pragma unroll
        for (int i = 0; i < 4; i++)
            pa[i] = *(const float4*)(in + (size_t)(m0 + arow[i]) * DI + kc + acol);
#pragma unroll
        for (int i = 0; i < 4; i++) {
            const float* Wp = wsel[i] ? Wf : Wx;
            pw[i] = *(const float4*)(Wp + (size_t)(o0 + wrow[i]) * DI + kc + wcol[i]);
        }
    };
    auto sts = [&](int s) {
        uint32_t* S = smem + s * STG_W;
#pragma unroll
        for (int i = 0; i < 4; i++) {
            uint2 v;
            v.x = packh2(pa[i].x, pa[i].y);
            v.y = packh2(pa[i].z, pa[i].w);
            *(uint2*)(S + arow[i] * ASTR + (acol >> 1)) = v;
        }
#pragma unroll
        for (int i = 0; i < 4; i++) {
            uint2 v;
            v.x = packh2(pw[i].x, pw[i].y);
            v.y = packh2(pw[i].z, pw[i].w);
            *(uint2*)(S + AW + (wsel[i] * 64 + wrow[i]) * ASTR + (wcol[i] >> 1)) = v;
        }
    };

    ldg_issue(0);
    sts(0);
    __syncthreads();

    const int NCHK = DI / 32;   // 8 K-chunks of 32 (= 2 k16 steps each)
#pragma unroll 1
    for (int i = 0; i < NCHK; i++) {
        if (i < NCHK - 1) ldg_issue((i + 1) * 32);   // overlap with MMAs below

        const uint32_t* A  = smem + (i & 1) * STG_W;
        const uint32_t* W0 = A + AW;                 // Wx rows
        const uint32_t* W1 = W0 + 64 * ASTR;         // Wf rows

#pragma unroll
        for (int ks = 0; ks < 2; ks++) {             // k16 steps within chunk
            const int kw = ks * 8;                   // word offset
            uint32_t a[2][4];
#pragma unroll
            for (int mf = 0; mf < 2; mf++) {
                int rb = (warpM * 32 + mf * 16 + gid) * ASTR + kw + tig;
                a[mf][0] = A[rb];
                a[mf][1] = A[rb + 8 * ASTR];
                a[mf][2] = A[rb + 4];
                a[mf][3] = A[rb + 8 * ASTR + 4];
            }
#pragma unroll
            for (int nf = 0; nf < 4; nf++) {
                int ob = (warpN * 32 + nf * 8 + gid) * ASTR + kw + tig;
                uint32_t wx0 = W0[ob], wx1 = W0[ob + 4];
                uint32_t wf0 = W1[ob], wf1 = W1[ob + 4];
#pragma unroll
                for (int mf = 0; mf < 2; mf++) {
                    MMA_F16(accx[mf][nf], a[mf], wx0, wx1);
                    MMA_F16(accf[mf][nf], a[mf], wf0, wf1);
                }
            }
        }
        __syncthreads();              // all reads of stage i&1 done
        if (i < NCHK - 1) {
            sts((i + 1) & 1);
            __syncthreads();          // stage (i+1)&1 ready
        }
    }

    // ---- Epilogue: activations, write (a,b) to gmem AND smem for carry ----
    float2* sAB = (float2*)smem;       // [128 rows][64 o-cols], 64 KB (reuses stages)

#pragma unroll
    for (int mf = 0; mf < 2; mf++) {
#pragma unroll
        for (int rr = 0; rr < 2; rr++) {
            int rloc = warpM * 32 + mf * 16 + rr * 8 + gid;
            int m = m0 + rloc;
            float mk = mask[m] * 10000.0f;
#pragma unroll
            for (int nf = 0; nf < 4; nf++) {
                int oloc = warpN * 32 + nf * 8 + 2 * tig;
                int o = o0 + oloc;
                float zx0 = accx[mf][nf][rr * 2 + 0] + bx[o];
                float zx1 = accx[mf][nf][rr * 2 + 1] + bx[o + 1];
                float zf0 = accf[mf][nf][rr * 2 + 0] + bf[o] + mk;
                float zf1 = accf[mf][nf][rr * 2 + 1] + bf[o + 1] + mk;
                float x0 = __fdividef(2.0f, 1.0f + __expf(-2.0f * zx0)) - 1.0f;
                float x1 = __fdividef(2.0f, 1.0f + __expf(-2.0f * zx1)) - 1.0f;
                float f0 = __fdividef(1.0f, 1.0f + __expf(-zf0));
                float f1 = __fdividef(1.0f, 1.0f + __expf(-zf1));
                float4 st;
                st.x = 1.0f - f0; st.y = f0 * x0;
                st.z = 1.0f - f1; st.w = f1 * x1;
                *(float4*)(&g_ab[((size_t)m * DO + o) * 2]) = st;
                *(float4*)(&sAB[rloc * 64 + oloc]) = st;
            }
        }
    }
    __syncthreads();

    // ---- Fused carry: 4 segments of 32 rows -> 2 half-chunk carries ----
    {
        const int o   = tid & 63;
        const int seg = tid >> 6;          // 0..3
        const float2* col = sAB + seg * 32 * 64 + o;
        float A = 1.0f, S = 0.0f;
#pragma unroll 8
        for (int r = 0; r < 32; r++) {
            float2 v = col[r * 64];
            S = fmaf(v.x, S, v.y);
            A = A * v.x;
        }
        sSeg[seg][o] = make_float2(A, S);
    }
    __syncthreads();

    if (tid < 128) {
        const int o    = tid & 63;
        const int half = tid >> 6;         // 0..1
        float2 s0 = sSeg[2 * half][o];
        float2 s1 = sSeg[2 * half + 1][o];
        float A = s1.x * s0.x;
        float S = fmaf(s1.x, s0.y, s1.y);
        const int b = blockIdx.y >> 5;           // 32 m-tiles per sequence
        const int c = blockIdx.y & 31;           // 128-row chunk within sequence
        const int idx = (b * NCH + c * 2 + half) * DO + o0 + o;
        g_cA[idx] = A;
        g_cS[idx] = S;
    }
}

// Phase 2: per-chain serial combine over NCH half-chunk carries.
__global__ __launch_bounds__(256) void scan_combine()
{
    const int b = blockIdx.x;
    const int o = threadIdx.x;

    float h = 0.0f;
#pragma unroll 4
    for (int c = 0; c < NCH; c++) {
        const int idx = (b * NCH + c) * DO + o;
        g_hin[idx] = h;
        h = fmaf(g_cA[idx], h, g_cS[idx]);
    }
}

// Phase 3: re-scan each half-chunk from its exact entry state, writing output.
// One thread handles TWO adjacent chains: LDG.128 + STG.64 per step.
__global__ __launch_bounds__(128) void scan_apply(float* __restrict__ out)
{
    const int b = blockIdx.x;
    const int c = blockIdx.y;
    const int j = threadIdx.x;            // 0..127 -> chains 2j, 2j+1

    const size_t rowbase = ((size_t)b * T_ + (size_t)c * CHUNK) * DO;
    const float4* __restrict__ ab = (const float4*)(g_ab + (rowbase + 2 * j) * 2);
    float2* __restrict__ op = (float2*)(out + rowbase) + j;

    const int hidx = (b * NCH + c) * DO + 2 * j;
    float h0 = g_hin[hidx];
    float h1 = g_hin[hidx + 1];

#pragma unroll 8
    for (int t = 0; t < CHUNK; t++) {
        float4 v = ab[(size_t)t * (DO / 2)];   // (a0,b0,a1,b1)
        h0 = fmaf(v.x, h0, v.y);
        h1 = fmaf(v.z, h1, v.w);
        op[(size_t)t * (DO / 2)] = make_float2(h0, h1);
    }
}

extern "C" void kernel_launch(void* const* d_in, const int* in_sizes, int n_in,
                              void* d_out, int out_size)
{
    const float* in   = (const float*)d_in[0];
    const float* mask = (const float*)d_in[1];
    const float* Wx   = (const float*)d_in[2];
    const float* bx   = (const float*)d_in[3];
    const float* Wf   = (const float*)d_in[4];
    const float* bf   = (const float*)d_in[5];
    float* out = (float*)d_out;

    static bool attr_set = false;
    if (!attr_set) {
        cudaFuncSetAttribute(qrnn_gemm,
                             cudaFuncAttributeMaxDynamicSharedMemorySize,
                             SMEM_WORDS * (int)sizeof(uint32_t));
        attr_set = true;
    }

    dim3 ggrid(DO / 64, M_TOTAL / MTILE);   // (4, 256)
    qrnn_gemm<<<ggrid, 256, SMEM_WORDS * sizeof(uint32_t)>>>(in, mask, Wx, bx, Wf, bf);

    scan_combine<<<B_, 256>>>();
    dim3 sgrid(B_, NCH);                    // (8, 64)
    scan_apply<<<sgrid, 128>>>(out);
}